// round 13
// baseline (speedup 1.0000x reference)
#include <cuda_runtime.h>
#include <math.h>
#include <stdint.h>

#define BB     2
#define NN     4096
#define QDIM   512
#define HEADS  8
#define DH     64
#define INNER  512
#define ROWS   (BB * NN)          // 8192
// 64^-0.5 * log2(e): S computed in log2 domain, P = ex2(S)
#define SCALE_L2E  (0.125f * 1.4426950408889634f)

#define QSTR   72      // Ks row stride: conflict-free paired (LDS.64) k-loads
#define VSTR   68      // Vs row stride: conflict-free scalar column loads
#define NT     (NN / 64)
#define WN     (512 * 512)

// Scratch (device globals: allocation-free per harness rules)
__device__ float g_Q[(size_t)ROWS * INNER];
__device__ float g_K[(size_t)ROWS * INNER];
__device__ float g_V[(size_t)ROWS * INNER];
__device__ float g_OH[(size_t)ROWS * INNER];   // attention output, hi part
__device__ float g_OL[(size_t)ROWS * INNER];   // attention output, lo part
__device__ float g_XH[(size_t)ROWS * QDIM];    // x split hi
__device__ float g_XL[(size_t)ROWS * QDIM];    // x split lo
__device__ float g_WR[(size_t)4 * WN];         // Wq,Wk,Wv,Wo RNA-rounded

// ---------------------------------------------------------------------------
// helpers
// ---------------------------------------------------------------------------
__device__ __forceinline__ uint32_t f2tf(float x) {
    uint32_t u;
    asm("cvt.rna.tf32.f32 %0, %1;" : "=r"(u) : "f"(x));
    return u;
}

__device__ __forceinline__ float ex2(float x) {
    float y;
    asm("ex2.approx.ftz.f32 %0, %1;" : "=f"(y) : "f"(x));
    return y;
}

__device__ __forceinline__ uint32_t fu(float x) { return __float_as_uint(x); }
__device__ __forceinline__ float uf(uint32_t x) { return __uint_as_float(x); }

__device__ __forceinline__ void mma_tf32(float d[4], uint32_t a0, uint32_t a1,
                                         uint32_t a2, uint32_t a3,
                                         uint32_t b0, uint32_t b1) {
    asm("mma.sync.aligned.m16n8k8.row.col.f32.tf32.tf32.f32 "
        "{%0,%1,%2,%3},{%4,%5,%6,%7},{%8,%9},{%0,%1,%2,%3};"
        : "+f"(d[0]), "+f"(d[1]), "+f"(d[2]), "+f"(d[3])
        : "r"(a0), "r"(a1), "r"(a2), "r"(a3), "r"(b0), "r"(b1));
}

__device__ __forceinline__ void split_tf(float x, uint32_t& hi, uint32_t& lo) {
    hi = f2tf(x);
    lo = f2tf(x - __uint_as_float(hi));
}

__device__ __forceinline__ void split4(float4 v, float4& h, float4& l) {
    uint32_t hx, lx, hy, ly, hz, lz, hw, lw;
    split_tf(v.x, hx, lx);
    split_tf(v.y, hy, ly);
    split_tf(v.z, hz, lz);
    split_tf(v.w, hw, lw);
    h = make_float4(uf(hx), uf(hy), uf(hz), uf(hw));
    l = make_float4(uf(lx), uf(ly), uf(lz), uf(lw));
}

__device__ __forceinline__ float4 rna4(float4 v) {
    return make_float4(uf(f2tf(v.x)), uf(f2tf(v.y)), uf(f2tf(v.z)), uf(f2tf(v.w)));
}

__device__ __forceinline__ void cp16(uint32_t dst, const void* src) {
    asm volatile("cp.async.cg.shared.global [%0], [%1], 16;" :: "r"(dst), "l"(src));
}

// ---------------------------------------------------------------------------
// Prep: split x -> (XH, XL); RNA-round Wq/Wk/Wv/Wo -> g_WR. One-time, ~10us.
// ---------------------------------------------------------------------------
#define NX4 (ROWS * QDIM / 4)        // 1048576 float4
#define NW4 (4 * WN / 4)             // 262144 float4

__global__ __launch_bounds__(256) void prep_kernel(const float* __restrict__ x,
                                                   const float* __restrict__ Wq,
                                                   const float* __restrict__ Wk,
                                                   const float* __restrict__ Wv,
                                                   const float* __restrict__ Wo) {
    int gid = blockIdx.x * 256 + threadIdx.x;
    if (gid < NX4) {
        float4 v = ((const float4*)x)[gid];
        float4 h, l;
        split4(v, h, l);
        ((float4*)g_XH)[gid] = h;
        ((float4*)g_XL)[gid] = l;
    } else if (gid < NX4 + NW4) {
        int g2 = gid - NX4;
        int w = g2 >> 16, off = g2 & 65535;
        const float* src = (w == 0) ? Wq : (w == 1) ? Wk : (w == 2) ? Wv : Wo;
        float4 v = ((const float4*)src)[off];
        ((float4*)(g_WR + (size_t)w * WN))[off] = rna4(v);
    }
}

// ---------------------------------------------------------------------------
// GEMM 2xTF32, all-cp.async, triple-buffered, ONE sync per k-tile. (unchanged)
// ---------------------------------------------------------------------------
#define ASTR 40
#define BSTR 260
#define GN   512
#define GKT  16

__device__ __forceinline__ void gemm_issue(const float* __restrict__ Ah,
                                           const float* __restrict__ Al,
                                           const float* __restrict__ Bw,
                                           int m0, int n0, int kt, int ib,
                                           uint32_t ah_u, uint32_t al_u,
                                           uint32_t bs_u) {
    const int tid = threadIdx.x;
#pragma unroll
    for (int i = 0; i < 2; i++) {
        int idx = tid + i * 512;
        int r = idx >> 3, c8 = idx & 7;
        uint32_t off = (uint32_t)(ib * 128 * ASTR + r * ASTR + c8 * 4) * 4;
        size_t goff = (size_t)(m0 + r) * 512 + kt * 32 + c8 * 4;
        cp16(ah_u + off, Ah + goff);
        cp16(al_u + off, Al + goff);
    }
#pragma unroll
    for (int i = 0; i < 4; i++) {
        int idx = tid + i * 512;
        int r = idx >> 6, c4 = idx & 63;
        cp16(bs_u + (uint32_t)(ib * 32 * BSTR + r * BSTR + c4 * 4) * 4,
             Bw + (size_t)(kt * 32 + r) * GN + n0 + c4 * 4);
    }
    asm volatile("cp.async.commit_group;");
}

__device__ __forceinline__ void gemm2x_core(const float* __restrict__ Ah,
                                            const float* __restrict__ Al,
                                            const float* __restrict__ Bw,
                                            const float* __restrict__ bias,
                                            float* __restrict__ C,
                                            int m0, int n0, float* smg,
                                            bool has_bias) {
    float* Ahs = smg;                        // [3][128][ASTR]
    float* Als = Ahs + 3 * 128 * ASTR;       // [3][128][ASTR]
    float* Bs  = Als + 3 * 128 * ASTR;       // [3][32][BSTR]

    const int tid = threadIdx.x;
    const int lane = tid & 31, wid = tid >> 5;
    const int t = lane & 3, g = lane >> 2;
    const int wm = wid >> 2, wn = wid & 3;   // 4m x 4n warps

    const uint32_t ah_u = (uint32_t)__cvta_generic_to_shared(Ahs);
    const uint32_t al_u = (uint32_t)__cvta_generic_to_shared(Als);
    const uint32_t bs_u = (uint32_t)__cvta_generic_to_shared(Bs);

    gemm_issue(Ah, Al, Bw, m0, n0, 0, 0, ah_u, al_u, bs_u);
    gemm_issue(Ah, Al, Bw, m0, n0, 1, 1, ah_u, al_u, bs_u);

    float acc[2][8][4];
#pragma unroll
    for (int i = 0; i < 2; i++)
#pragma unroll
        for (int j = 0; j < 8; j++)
#pragma unroll
            for (int e = 0; e < 4; e++) acc[i][j][e] = 0.f;

    int cur = 0;
    for (int kt = 0; kt < GKT; kt++) {
        if (kt + 1 < GKT)
            asm volatile("cp.async.wait_group 1;");
        else
            asm volatile("cp.async.wait_group 0;");
        __syncthreads();   // tile kt visible; all warps done with tile kt-1

        if (kt + 2 < GKT) {
            int ib = cur + 2;
            if (ib >= 3) ib -= 3;
            gemm_issue(Ah, Al, Bw, m0, n0, kt + 2, ib, ah_u, al_u, bs_u);
        }

        const float* ah = Ahs + cur * 128 * ASTR;
        const float* al = Als + cur * 128 * ASTR;
        const float* bs = Bs + cur * 32 * BSTR;

#pragma unroll
        for (int kk = 0; kk < 32; kk += 8) {
            uint32_t Am[2][4], Al2[2][4];
#pragma unroll
            for (int mt = 0; mt < 2; mt++) {
                int mb = wm * 32 + mt * 16;
                float2 h0 = *(const float2*)&ah[(mb + g) * ASTR + kk + 2 * t];
                float2 h1 = *(const float2*)&ah[(mb + g + 8) * ASTR + kk + 2 * t];
                float2 l0 = *(const float2*)&al[(mb + g) * ASTR + kk + 2 * t];
                float2 l1 = *(const float2*)&al[(mb + g + 8) * ASTR + kk + 2 * t];
                Am[mt][0] = fu(h0.x); Am[mt][1] = fu(h1.x);
                Am[mt][2] = fu(h0.y); Am[mt][3] = fu(h1.y);
                Al2[mt][0] = fu(l0.x); Al2[mt][1] = fu(l1.x);
                Al2[mt][2] = fu(l0.y); Al2[mt][3] = fu(l1.y);
            }
#pragma unroll
            for (int nt = 0; nt < 8; nt++) {
                int nb = wn * 64 + nt * 8;
                uint32_t b0 = fu(bs[(kk + 2 * t) * BSTR + nb + g]);
                uint32_t b1 = fu(bs[(kk + 2 * t + 1) * BSTR + nb + g]);
#pragma unroll
                for (int mt = 0; mt < 2; mt++) {
                    mma_tf32(acc[mt][nt], Am[mt][0], Am[mt][1], Am[mt][2], Am[mt][3],
                             b0, b1);
                    mma_tf32(acc[mt][nt], Al2[mt][0], Al2[mt][1], Al2[mt][2],
                             Al2[mt][3], b0, b1);
                }
            }
        }
        cur = (cur == 2) ? 0 : cur + 1;
    }

    // epilogue
#pragma unroll
    for (int mt = 0; mt < 2; mt++) {
#pragma unroll
        for (int nt = 0; nt < 8; nt++) {
            int r = m0 + wm * 32 + mt * 16 + g;
            int c = n0 + wn * 64 + nt * 8 + 2 * t;
            float b0 = has_bias ? bias[c] : 0.f;
            float b1 = has_bias ? bias[c + 1] : 0.f;
            float2 v0 = make_float2(acc[mt][nt][0] + b0, acc[mt][nt][1] + b1);
            float2 v1 = make_float2(acc[mt][nt][2] + b0, acc[mt][nt][3] + b1);
            *(float2*)&C[(size_t)r * GN + c] = v0;
            *(float2*)&C[(size_t)(r + 8) * GN + c] = v1;
        }
    }
}

// Fused QKV projection: grid.x = 6 (3 matrices x 2 n-blocks of 256)
__global__ __launch_bounds__(512, 1) void gemm_qkv(float* __restrict__ Qd,
                                                   float* __restrict__ Kd,
                                                   float* __restrict__ Vd) {
    extern __shared__ float smg[];
    const int sel = blockIdx.x >> 1;
    const float* Bw = g_WR + (size_t)sel * WN;
    float* C = (sel == 0) ? Qd : (sel == 1) ? Kd : Vd;
    gemm2x_core(g_XH, g_XL, Bw, nullptr, C, blockIdx.y * 128,
                (blockIdx.x & 1) * 256, smg, false);
}

// Output projection (with bias): grid.x = 2
__global__ __launch_bounds__(512, 1) void gemm_out(const float* __restrict__ bo,
                                                   float* __restrict__ out) {
    extern __shared__ float smg[];
    gemm2x_core(g_OH, g_OL, g_WR + (size_t)3 * WN, bo, out, blockIdx.y * 128,
                blockIdx.x * 256, smg, true);
}

// ---------------------------------------------------------------------------
// Flash attention v7: m32 per warp (rows g,g+8,g+16,g+24), 1 CTA/SM, full
// register budget. K/V smem reads amortized over BOTH m-tiles in one pass:
// per-SM smem traffic per KV tile halves vs v6. Q fragments in registers;
// K+V triple-buffered cp.async; ONE __syncthreads per KV tile.
// Softmax in log2 domain, no max-subtraction. Writes O split hi/lo.
// ---------------------------------------------------------------------------
__device__ __forceinline__ void attn_issue(const float* __restrict__ Kp,
                                           const float* __restrict__ Vp,
                                           int tile, int ib, uint32_t ks_u,
                                           uint32_t vs_u, int lr, int lc) {
    const size_t cb = (size_t)tile * 64;
#pragma unroll
    for (int i = 0; i < 4; i++) {
        int rr = lr + i * 16;
        cp16(ks_u + (uint32_t)(ib * 64 * QSTR + rr * QSTR + lc * 4) * 4,
             Kp + (cb + rr) * INNER + lc * 4);
        cp16(vs_u + (uint32_t)(ib * 64 * VSTR + rr * VSTR + lc * 4) * 4,
             Vp + (cb + rr) * INNER + lc * 4);
    }
    asm volatile("cp.async.commit_group;");
}

__global__ __launch_bounds__(256, 1) void attn_tc7() {
    extern __shared__ float sm[];
    float* Ks = sm;                     // [3][64][QSTR]
    float* Vs = sm + 3 * 64 * QSTR;     // [3][64][VSTR]

    const int tid = threadIdx.x;
    const int lane = tid & 31, wid = tid >> 5;
    const int t = lane & 3, g = lane >> 2;
    const int b = blockIdx.z, h = blockIdx.y;
    const int r0 = blockIdx.x * 256;
    const int mb = wid * 32;            // warp's 32-row base

    const float* Kp = g_K + ((size_t)b * NN) * INNER + h * DH;
    const float* Vp = g_V + ((size_t)b * NN) * INNER + h * DH;

    const uint32_t ks_u = (uint32_t)__cvta_generic_to_shared(Ks);
    const uint32_t vs_u = (uint32_t)__cvta_generic_to_shared(Vs);
    const int lr = tid >> 4, lc = tid & 15;

    // --- pre-issue KV tiles 0,1 into bufs 0,1 ---
    attn_issue(Kp, Vp, 0, 0, ks_u, vs_u, lr, lc);
    attn_issue(Kp, Vp, 1, 1, ks_u, vs_u, lr, lc);

    // --- Q fragments in registers: rows mb+g, +8, +16, +24 ---
    float2 qa[8], qb[8], qc[8], qd[8];
    {
        const size_t row = (size_t)b * NN + r0 + mb + g;
        const float* q0 = g_Q + row * INNER + h * DH;
#pragma unroll
        for (int k8 = 0; k8 < 8; k8++) {
            float2 v0 = *(const float2*)&q0[k8 * 8 + 2 * t];
            float2 v1 = *(const float2*)&q0[8 * INNER + k8 * 8 + 2 * t];
            float2 v2 = *(const float2*)&q0[16 * INNER + k8 * 8 + 2 * t];
            float2 v3 = *(const float2*)&q0[24 * INNER + k8 * 8 + 2 * t];
            qa[k8] = make_float2(uf(f2tf(v0.x * SCALE_L2E)), uf(f2tf(v0.y * SCALE_L2E)));
            qb[k8] = make_float2(uf(f2tf(v1.x * SCALE_L2E)), uf(f2tf(v1.y * SCALE_L2E)));
            qc[k8] = make_float2(uf(f2tf(v2.x * SCALE_L2E)), uf(f2tf(v2.y * SCALE_L2E)));
            qd[k8] = make_float2(uf(f2tf(v3.x * SCALE_L2E)), uf(f2tf(v3.y * SCALE_L2E)));
        }
    }

    float o[2][8][4];
#pragma unroll
    for (int mt = 0; mt < 2; mt++)
#pragma unroll
        for (int nt = 0; nt < 8; nt++)
#pragma unroll
            for (int e = 0; e < 4; e++) o[mt][nt][e] = 0.f;
    float l0 = 0.f, l1 = 0.f, l2 = 0.f, l3 = 0.f;

    int cur = 0;
    for (int it = 0; it < NT; ++it) {
        if (it + 1 < NT)
            asm volatile("cp.async.wait_group 1;");
        else
            asm volatile("cp.async.wait_group 0;");
        __syncthreads();   // tile it visible; all warps done with tile it-1

        if (it + 2 < NT) {
            int ib = cur + 2;
            if (ib >= 3) ib -= 3;
            attn_issue(Kp, Vp, it + 2, ib, ks_u, vs_u, lr, lc);
        }

        const float* Kb = Ks + cur * 64 * QSTR;
        const float* Vb = Vs + cur * 64 * VSTR;

        // ---- S = Q @ K^T : K pair load SHARED by both m-tiles ----
        float s[2][8][4];
#pragma unroll
        for (int mt = 0; mt < 2; mt++)
#pragma unroll
            for (int nt = 0; nt < 8; nt++)
#pragma unroll
                for (int e = 0; e < 4; e++) s[mt][nt][e] = 0.f;

#pragma unroll
        for (int k8 = 0; k8 < 8; k8++) {
            uint32_t a00 = fu(qa[k8].x), a01 = fu(qb[k8].x);
            uint32_t a02 = fu(qa[k8].y), a03 = fu(qb[k8].y);
            uint32_t a10 = fu(qc[k8].x), a11 = fu(qd[k8].x);
            uint32_t a12 = fu(qc[k8].y), a13 = fu(qd[k8].y);
#pragma unroll
            for (int nt = 0; nt < 8; nt++) {
                float2 kv = *(const float2*)&Kb[(nt * 8 + g) * QSTR + k8 * 8 + 2 * t];
                uint32_t b0 = fu(kv.x), b1 = fu(kv.y);
                mma_tf32(s[0][nt], a00, a01, a02, a03, b0, b1);
                mma_tf32(s[1][nt], a10, a11, a12, a13, b0, b1);
            }
        }

        // ---- P = ex2(S) (RNA tf32; consistent with rowsums), rowsums ----
#pragma unroll
        for (int nt = 0; nt < 8; nt++) {
#pragma unroll
            for (int e = 0; e < 4; e++) {
                s[0][nt][e] = uf(f2tf(ex2(s[0][nt][e])));
                s[1][nt][e] = uf(f2tf(ex2(s[1][nt][e])));
            }
            l0 += s[0][nt][0] + s[0][nt][1];
            l1 += s[0][nt][2] + s[0][nt][3];
            l2 += s[1][nt][0] + s[1][nt][1];
            l3 += s[1][nt][2] + s[1][nt][3];
        }

        // ---- O += P @ V : V loads SHARED by both m-tiles ----
#pragma unroll
        for (int kc = 0; kc < 8; kc++) {
            uint32_t a00 = fu(s[0][kc][0]), a01 = fu(s[0][kc][2]);
            uint32_t a02 = fu(s[0][kc][1]), a03 = fu(s[0][kc][3]);
            uint32_t a10 = fu(s[1][kc][0]), a11 = fu(s[1][kc][2]);
            uint32_t a12 = fu(s[1][kc][1]), a13 = fu(s[1][kc][3]);
            const int kb = kc * 8;
#pragma unroll
            for (int nt = 0; nt < 8; nt++) {
                uint32_t b0 = fu(Vb[(kb + 2 * t) * VSTR + nt * 8 + g]);
                uint32_t b1 = fu(Vb[(kb + 2 * t + 1) * VSTR + nt * 8 + g]);
                mma_tf32(o[0][nt], a00, a01, a02, a03, b0, b1);
                mma_tf32(o[1][nt], a10, a11, a12, a13, b0, b1);
            }
        }
        cur = (cur == 2) ? 0 : cur + 1;
    }

    // ---- rowsum reduction (within quad) and split writeout ----
    l0 += __shfl_xor_sync(0xffffffffu, l0, 1);
    l0 += __shfl_xor_sync(0xffffffffu, l0, 2);
    l1 += __shfl_xor_sync(0xffffffffu, l1, 1);
    l1 += __shfl_xor_sync(0xffffffffu, l1, 2);
    l2 += __shfl_xor_sync(0xffffffffu, l2, 1);
    l2 += __shfl_xor_sync(0xffffffffu, l2, 2);
    l3 += __shfl_xor_sync(0xffffffffu, l3, 1);
    l3 += __shfl_xor_sync(0xffffffffu, l3, 2);
    const float inv[4] = {1.f / l0, 1.f / l1, 1.f / l2, 1.f / l3};

    const size_t row = (size_t)b * NN + r0 + mb + g;
    const size_t base = row * INNER + h * DH;
#pragma unroll
    for (int mt = 0; mt < 2; mt++) {
        const size_t b0 = base + (size_t)(mt * 16) * INNER;
        const size_t b1 = b0 + 8 * INNER;
        const float i0 = inv[mt * 2], i1 = inv[mt * 2 + 1];
#pragma unroll
        for (int nt = 0; nt < 8; nt++) {
            int c = nt * 8 + 2 * t;
            float v00 = o[mt][nt][0] * i0, v01 = o[mt][nt][1] * i0;
            float v10 = o[mt][nt][2] * i1, v11 = o[mt][nt][3] * i1;
            uint32_t h00, l00, h01, l01, h10, l10, h11, l11;
            split_tf(v00, h00, l00);
            split_tf(v01, h01, l01);
            split_tf(v10, h10, l10);
            split_tf(v11, h11, l11);
            *(float2*)&g_OH[b0 + c] = make_float2(uf(h00), uf(h01));
            *(float2*)&g_OL[b0 + c] = make_float2(uf(l00), uf(l01));
            *(float2*)&g_OH[b1 + c] = make_float2(uf(h10), uf(h11));
            *(float2*)&g_OL[b1 + c] = make_float2(uf(l10), uf(l11));
        }
    }
}

// ---------------------------------------------------------------------------
extern "C" void kernel_launch(void* const* d_in, const int* in_sizes, int n_in,
                              void* d_out, int out_size) {
    const float* x  = (const float*)d_in[0];
    const float* Wq = (const float*)d_in[1];
    const float* Wk = (const float*)d_in[2];
    const float* Wv = (const float*)d_in[3];
    const float* Wo = (const float*)d_in[4];
    const float* bo = (const float*)d_in[5];
    float* out = (float*)d_out;

    float *Qp, *Kp, *Vp;
    cudaGetSymbolAddress((void**)&Qp, g_Q);
    cudaGetSymbolAddress((void**)&Kp, g_K);
    cudaGetSymbolAddress((void**)&Vp, g_V);

    const int smem_gemm =
        (3 * (2 * 128 * ASTR) + 3 * 32 * BSTR) * sizeof(float);      // 222720 B
    const int smem_attn = (3 * 64 * (QSTR + VSTR)) * sizeof(float);  // 107520 B

    cudaFuncSetAttribute(gemm_qkv, cudaFuncAttributeMaxDynamicSharedMemorySize,
                         smem_gemm);
    cudaFuncSetAttribute(gemm_out, cudaFuncAttributeMaxDynamicSharedMemorySize,
                         smem_gemm);
    cudaFuncSetAttribute(attn_tc7, cudaFuncAttributeMaxDynamicSharedMemorySize,
                         smem_attn);

    prep_kernel<<<(NX4 + NW4 + 255) / 256, 256>>>(x, Wq, Wk, Wv, Wo);

    gemm_qkv<<<dim3(6, ROWS / 128), 512, smem_gemm>>>(Qp, Kp, Vp);

    attn_tc7<<<dim3(NN / 256, HEADS, BB), 256, smem_attn>>>();

    gemm_out<<<dim3(2, ROWS / 128), 512, smem_gemm>>>(bo, out);
}

// round 14
// speedup vs baseline: 1.4653x; 1.4653x over previous
#include <cuda_runtime.h>
#include <math.h>
#include <stdint.h>

#define BB     2
#define NN     4096
#define QDIM   512
#define HEADS  8
#define DH     64
#define INNER  512
#define ROWS   (BB * NN)          // 8192
// 64^-0.5 * log2(e): S computed in log2 domain, P = ex2(S)
#define SCALE_L2E  (0.125f * 1.4426950408889634f)

#define QSTR   72      // Ks row stride: conflict-free paired (LDS.64) k-loads
#define VSTR   68      // Vs row stride: conflict-free scalar column loads
#define NT     (NN / 64)
#define WN     (512 * 512)

// Scratch (device globals: allocation-free per harness rules)
__device__ float g_Q[(size_t)ROWS * INNER];
__device__ float g_K[(size_t)ROWS * INNER];
__device__ float g_V[(size_t)ROWS * INNER];
__device__ float g_OH[(size_t)ROWS * INNER];   // attention output, hi part
__device__ float g_OL[(size_t)ROWS * INNER];   // attention output, lo part
__device__ float g_XH[(size_t)ROWS * QDIM];    // x split hi
__device__ float g_XL[(size_t)ROWS * QDIM];    // x split lo
__device__ float g_WR[(size_t)4 * WN];         // Wq,Wk,Wv,Wo RNA-rounded

// ---------------------------------------------------------------------------
// helpers
// ---------------------------------------------------------------------------
__device__ __forceinline__ uint32_t f2tf(float x) {
    uint32_t u;
    asm("cvt.rna.tf32.f32 %0, %1;" : "=r"(u) : "f"(x));
    return u;
}

__device__ __forceinline__ float ex2(float x) {
    float y;
    asm("ex2.approx.ftz.f32 %0, %1;" : "=f"(y) : "f"(x));
    return y;
}

__device__ __forceinline__ uint32_t fu(float x) { return __float_as_uint(x); }
__device__ __forceinline__ float uf(uint32_t x) { return __uint_as_float(x); }

__device__ __forceinline__ void mma_tf32(float d[4], uint32_t a0, uint32_t a1,
                                         uint32_t a2, uint32_t a3,
                                         uint32_t b0, uint32_t b1) {
    asm("mma.sync.aligned.m16n8k8.row.col.f32.tf32.tf32.f32 "
        "{%0,%1,%2,%3},{%4,%5,%6,%7},{%8,%9},{%0,%1,%2,%3};"
        : "+f"(d[0]), "+f"(d[1]), "+f"(d[2]), "+f"(d[3])
        : "r"(a0), "r"(a1), "r"(a2), "r"(a3), "r"(b0), "r"(b1));
}

__device__ __forceinline__ void split_tf(float x, uint32_t& hi, uint32_t& lo) {
    hi = f2tf(x);
    lo = f2tf(x - __uint_as_float(hi));
}

__device__ __forceinline__ void split4(float4 v, float4& h, float4& l) {
    uint32_t hx, lx, hy, ly, hz, lz, hw, lw;
    split_tf(v.x, hx, lx);
    split_tf(v.y, hy, ly);
    split_tf(v.z, hz, lz);
    split_tf(v.w, hw, lw);
    h = make_float4(uf(hx), uf(hy), uf(hz), uf(hw));
    l = make_float4(uf(lx), uf(ly), uf(lz), uf(lw));
}

__device__ __forceinline__ float4 rna4(float4 v) {
    return make_float4(uf(f2tf(v.x)), uf(f2tf(v.y)), uf(f2tf(v.z)), uf(f2tf(v.w)));
}

__device__ __forceinline__ void cp16(uint32_t dst, const void* src) {
    asm volatile("cp.async.cg.shared.global [%0], [%1], 16;" :: "r"(dst), "l"(src));
}

// ---------------------------------------------------------------------------
// Prep: split x -> (XH, XL); RNA-round Wq/Wk/Wv/Wo -> g_WR. One-time, ~10us.
// ---------------------------------------------------------------------------
#define NX4 (ROWS * QDIM / 4)        // 1048576 float4
#define NW4 (4 * WN / 4)             // 262144 float4

__global__ __launch_bounds__(256) void prep_kernel(const float* __restrict__ x,
                                                   const float* __restrict__ Wq,
                                                   const float* __restrict__ Wk,
                                                   const float* __restrict__ Wv,
                                                   const float* __restrict__ Wo) {
    int gid = blockIdx.x * 256 + threadIdx.x;
    if (gid < NX4) {
        float4 v = ((const float4*)x)[gid];
        float4 h, l;
        split4(v, h, l);
        ((float4*)g_XH)[gid] = h;
        ((float4*)g_XL)[gid] = l;
    } else if (gid < NX4 + NW4) {
        int g2 = gid - NX4;
        int w = g2 >> 16, off = g2 & 65535;
        const float* src = (w == 0) ? Wq : (w == 1) ? Wk : (w == 2) ? Wv : Wo;
        float4 v = ((const float4*)src)[off];
        ((float4*)(g_WR + (size_t)w * WN))[off] = rna4(v);
    }
}

// ---------------------------------------------------------------------------
// GEMM 2xTF32, all-cp.async, triple-buffered, ONE sync per k-tile.
// Strength-reduced addressing: per-thread global/smem base offsets hoisted;
// per-issue address = base + (kt<<5)[*GN] adds only.
// ---------------------------------------------------------------------------
#define ASTR 40
#define BSTR 260
#define GN   512
#define GKT  16

struct GemmPtrs {
    const float* a0h;  // Ah + r0*512 + c0*4   (A loader row 0)
    const float* a1h;  // Ah + r1*512 + c1*4   (A loader row 1)
    const float* a0l;
    const float* a1l;
    const float* b0;   // Bw + r_i*GN + c_i*4, i = 0..3
    const float* b1;
    const float* b2;
    const float* b3;
    uint32_t aOff0, aOff1;  // smem float-offsets within one A buffer
    uint32_t bOff0, bOff1, bOff2, bOff3;
};

__device__ __forceinline__ void gemm_issue2(const GemmPtrs& P, int kt, int ib,
                                            uint32_t ah_u, uint32_t al_u,
                                            uint32_t bs_u) {
    const int ka = kt * 32;                 // A column advance (floats)
    const size_t kb = (size_t)ka * GN;      // B row advance (floats)
    const uint32_t abuf = ah_u + (uint32_t)(ib * 128 * ASTR) * 4;
    const uint32_t lbuf = al_u + (uint32_t)(ib * 128 * ASTR) * 4;
    const uint32_t bbuf = bs_u + (uint32_t)(ib * 32 * BSTR) * 4;
    cp16(abuf + P.aOff0 * 4, P.a0h + ka);
    cp16(lbuf + P.aOff0 * 4, P.a0l + ka);
    cp16(abuf + P.aOff1 * 4, P.a1h + ka);
    cp16(lbuf + P.aOff1 * 4, P.a1l + ka);
    cp16(bbuf + P.bOff0 * 4, P.b0 + kb);
    cp16(bbuf + P.bOff1 * 4, P.b1 + kb);
    cp16(bbuf + P.bOff2 * 4, P.b2 + kb);
    cp16(bbuf + P.bOff3 * 4, P.b3 + kb);
    asm volatile("cp.async.commit_group;");
}

__device__ __forceinline__ void gemm2x_core(const float* __restrict__ Ah,
                                            const float* __restrict__ Al,
                                            const float* __restrict__ Bw,
                                            const float* __restrict__ bias,
                                            float* __restrict__ C,
                                            int m0, int n0, float* smg,
                                            bool has_bias) {
    float* Ahs = smg;                        // [3][128][ASTR]
    float* Als = Ahs + 3 * 128 * ASTR;       // [3][128][ASTR]
    float* Bs  = Als + 3 * 128 * ASTR;       // [3][32][BSTR]

    const int tid = threadIdx.x;
    const int lane = tid & 31, wid = tid >> 5;
    const int t = lane & 3, g = lane >> 2;
    const int wm = wid >> 2, wn = wid & 3;   // 4m x 4n warps

    const uint32_t ah_u = (uint32_t)__cvta_generic_to_shared(Ahs);
    const uint32_t al_u = (uint32_t)__cvta_generic_to_shared(Als);
    const uint32_t bs_u = (uint32_t)__cvta_generic_to_shared(Bs);

    // hoisted per-thread loader geometry
    GemmPtrs P;
    {
        int r0 = tid >> 3, c0 = (tid & 7) * 4;            // A pass 0
        int r1 = (tid + 512) >> 3, c1 = ((tid + 512) & 7) * 4;
        P.a0h = Ah + (size_t)(m0 + r0) * 512 + c0;
        P.a1h = Ah + (size_t)(m0 + r1) * 512 + c1;
        P.a0l = Al + (size_t)(m0 + r0) * 512 + c0;
        P.a1l = Al + (size_t)(m0 + r1) * 512 + c1;
        P.aOff0 = (uint32_t)(r0 * ASTR + c0);
        P.aOff1 = (uint32_t)(r1 * ASTR + c1);
        int br[4], bc[4];
#pragma unroll
        for (int i = 0; i < 4; i++) {
            int idx = tid + i * 512;
            br[i] = idx >> 6;
            bc[i] = (idx & 63) * 4;
        }
        P.b0 = Bw + (size_t)br[0] * GN + n0 + bc[0];
        P.b1 = Bw + (size_t)br[1] * GN + n0 + bc[1];
        P.b2 = Bw + (size_t)br[2] * GN + n0 + bc[2];
        P.b3 = Bw + (size_t)br[3] * GN + n0 + bc[3];
        P.bOff0 = (uint32_t)(br[0] * BSTR + bc[0]);
        P.bOff1 = (uint32_t)(br[1] * BSTR + bc[1]);
        P.bOff2 = (uint32_t)(br[2] * BSTR + bc[2]);
        P.bOff3 = (uint32_t)(br[3] * BSTR + bc[3]);
    }

    gemm_issue2(P, 0, 0, ah_u, al_u, bs_u);
    gemm_issue2(P, 1, 1, ah_u, al_u, bs_u);

    float acc[2][8][4];
#pragma unroll
    for (int i = 0; i < 2; i++)
#pragma unroll
        for (int j = 0; j < 8; j++)
#pragma unroll
            for (int e = 0; e < 4; e++) acc[i][j][e] = 0.f;

    int cur = 0;
    for (int kt = 0; kt < GKT; kt++) {
        if (kt + 1 < GKT)
            asm volatile("cp.async.wait_group 1;");
        else
            asm volatile("cp.async.wait_group 0;");
        __syncthreads();   // tile kt visible; all warps done with tile kt-1

        if (kt + 2 < GKT) {
            int ib = cur + 2;
            if (ib >= 3) ib -= 3;
            gemm_issue2(P, kt + 2, ib, ah_u, al_u, bs_u);
        }

        const float* ah = Ahs + cur * 128 * ASTR;
        const float* al = Als + cur * 128 * ASTR;
        const float* bs = Bs + cur * 32 * BSTR;

#pragma unroll
        for (int kk = 0; kk < 32; kk += 8) {
            uint32_t Am[2][4], Al2[2][4];
#pragma unroll
            for (int mt = 0; mt < 2; mt++) {
                int mb = wm * 32 + mt * 16;
                float2 h0 = *(const float2*)&ah[(mb + g) * ASTR + kk + 2 * t];
                float2 h1 = *(const float2*)&ah[(mb + g + 8) * ASTR + kk + 2 * t];
                float2 l0 = *(const float2*)&al[(mb + g) * ASTR + kk + 2 * t];
                float2 l1 = *(const float2*)&al[(mb + g + 8) * ASTR + kk + 2 * t];
                Am[mt][0] = fu(h0.x); Am[mt][1] = fu(h1.x);
                Am[mt][2] = fu(h0.y); Am[mt][3] = fu(h1.y);
                Al2[mt][0] = fu(l0.x); Al2[mt][1] = fu(l1.x);
                Al2[mt][2] = fu(l0.y); Al2[mt][3] = fu(l1.y);
            }
#pragma unroll
            for (int nt = 0; nt < 8; nt++) {
                int nb = wn * 64 + nt * 8;
                uint32_t b0 = fu(bs[(kk + 2 * t) * BSTR + nb + g]);
                uint32_t b1 = fu(bs[(kk + 2 * t + 1) * BSTR + nb + g]);
#pragma unroll
                for (int mt = 0; mt < 2; mt++) {
                    mma_tf32(acc[mt][nt], Am[mt][0], Am[mt][1], Am[mt][2], Am[mt][3],
                             b0, b1);
                    mma_tf32(acc[mt][nt], Al2[mt][0], Al2[mt][1], Al2[mt][2],
                             Al2[mt][3], b0, b1);
                }
            }
        }
        cur = (cur == 2) ? 0 : cur + 1;
    }

    // epilogue
#pragma unroll
    for (int mt = 0; mt < 2; mt++) {
#pragma unroll
        for (int nt = 0; nt < 8; nt++) {
            int r = m0 + wm * 32 + mt * 16 + g;
            int c = n0 + wn * 64 + nt * 8 + 2 * t;
            float b0 = has_bias ? bias[c] : 0.f;
            float b1 = has_bias ? bias[c + 1] : 0.f;
            float2 v0 = make_float2(acc[mt][nt][0] + b0, acc[mt][nt][1] + b1);
            float2 v1 = make_float2(acc[mt][nt][2] + b0, acc[mt][nt][3] + b1);
            *(float2*)&C[(size_t)r * GN + c] = v0;
            *(float2*)&C[(size_t)(r + 8) * GN + c] = v1;
        }
    }
}

// Fused QKV projection: grid.x = 6 (3 matrices x 2 n-blocks of 256)
__global__ __launch_bounds__(512, 1) void gemm_qkv(float* __restrict__ Qd,
                                                   float* __restrict__ Kd,
                                                   float* __restrict__ Vd) {
    extern __shared__ float smg[];
    const int sel = blockIdx.x >> 1;
    const float* Bw = g_WR + (size_t)sel * WN;
    float* C = (sel == 0) ? Qd : (sel == 1) ? Kd : Vd;
    gemm2x_core(g_XH, g_XL, Bw, nullptr, C, blockIdx.y * 128,
                (blockIdx.x & 1) * 256, smg, false);
}

// Output projection (with bias): grid.x = 2
__global__ __launch_bounds__(512, 1) void gemm_out(const float* __restrict__ bo,
                                                   float* __restrict__ out) {
    extern __shared__ float smg[];
    gemm2x_core(g_OH, g_OL, g_WR + (size_t)3 * WN, bo, out, blockIdx.y * 128,
                blockIdx.x * 256, smg, true);
}

// ---------------------------------------------------------------------------
// Flash attention v6 (R12 verbatim, 657us anchor): Q fragments in registers;
// K+V triple-buffered cp.async; ONE __syncthreads per KV tile; LDS.64 S-phase
// K loads (k-slot perm, stride 72); conflict-free scalar PV loads (stride 68).
// 2 CTAs/SM. Softmax in log2 domain, no max-subtraction. O split hi/lo.
// ---------------------------------------------------------------------------
__device__ __forceinline__ void attn_issue(const float* __restrict__ Kp,
                                           const float* __restrict__ Vp,
                                           int tile, int ib, uint32_t ks_u,
                                           uint32_t vs_u, int lr, int lc) {
    const size_t cb = (size_t)tile * 64;
#pragma unroll
    for (int i = 0; i < 4; i++) {
        int rr = lr + i * 16;
        cp16(ks_u + (uint32_t)(ib * 64 * QSTR + rr * QSTR + lc * 4) * 4,
             Kp + (cb + rr) * INNER + lc * 4);
        cp16(vs_u + (uint32_t)(ib * 64 * VSTR + rr * VSTR + lc * 4) * 4,
             Vp + (cb + rr) * INNER + lc * 4);
    }
    asm volatile("cp.async.commit_group;");
}

__global__ __launch_bounds__(256, 2) void attn_tc6() {
    extern __shared__ float sm[];
    float* Ks = sm;                     // [3][64][QSTR]
    float* Vs = sm + 3 * 64 * QSTR;     // [3][64][VSTR]

    const int tid = threadIdx.x;
    const int lane = tid & 31, wid = tid >> 5;
    const int t = lane & 3, g = lane >> 2;
    const int b = blockIdx.z, h = blockIdx.y;
    const int r0 = blockIdx.x * 128;
    const int mb = wid * 16;

    const float* Kp = g_K + ((size_t)b * NN) * INNER + h * DH;
    const float* Vp = g_V + ((size_t)b * NN) * INNER + h * DH;

    const uint32_t ks_u = (uint32_t)__cvta_generic_to_shared(Ks);
    const uint32_t vs_u = (uint32_t)__cvta_generic_to_shared(Vs);
    const int lr = tid >> 4, lc = tid & 15;

    // --- pre-issue KV tiles 0,1 into bufs 0,1 ---
    attn_issue(Kp, Vp, 0, 0, ks_u, vs_u, lr, lc);
    attn_issue(Kp, Vp, 1, 1, ks_u, vs_u, lr, lc);

    // --- Q fragments in registers (each warp owns its 16 rows) ---
    float2 qa[8], qb[8];
    {
        const size_t row = (size_t)b * NN + r0 + mb + g;
        const float* q0 = g_Q + row * INNER + h * DH;
        const float* q1 = q0 + 8 * INNER;
#pragma unroll
        for (int k8 = 0; k8 < 8; k8++) {
            float2 v0 = *(const float2*)&q0[k8 * 8 + 2 * t];
            float2 v1 = *(const float2*)&q1[k8 * 8 + 2 * t];
            qa[k8] = make_float2(uf(f2tf(v0.x * SCALE_L2E)),
                                 uf(f2tf(v0.y * SCALE_L2E)));
            qb[k8] = make_float2(uf(f2tf(v1.x * SCALE_L2E)),
                                 uf(f2tf(v1.y * SCALE_L2E)));
        }
    }

    float o[8][4];
#pragma unroll
    for (int nt = 0; nt < 8; nt++)
#pragma unroll
        for (int e = 0; e < 4; e++) o[nt][e] = 0.f;
    float l0 = 0.f, l1 = 0.f;

    int cur = 0;
    for (int it = 0; it < NT; ++it) {
        if (it + 1 < NT)
            asm volatile("cp.async.wait_group 1;");
        else
            asm volatile("cp.async.wait_group 0;");
        __syncthreads();   // tile it visible; all warps done with tile it-1

        if (it + 2 < NT) {
            int ib = cur + 2;
            if (ib >= 3) ib -= 3;
            attn_issue(Kp, Vp, it + 2, ib, ks_u, vs_u, lr, lc);
        }

        const float* Kb = Ks + cur * 64 * QSTR;
        const float* Vb = Vs + cur * 64 * VSTR;

        // ---- S = Q @ K^T : K pair loads LDS.64 (k-slot perm t->2t) ----
        float s[8][4];
#pragma unroll
        for (int nt = 0; nt < 8; nt++)
#pragma unroll
            for (int e = 0; e < 4; e++) s[nt][e] = 0.f;

#pragma unroll
        for (int k8 = 0; k8 < 8; k8++) {
            uint32_t a0 = fu(qa[k8].x), a1 = fu(qb[k8].x);
            uint32_t a2 = fu(qa[k8].y), a3 = fu(qb[k8].y);
#pragma unroll
            for (int nt = 0; nt < 8; nt++) {
                float2 kv = *(const float2*)&Kb[(nt * 8 + g) * QSTR + k8 * 8 + 2 * t];
                mma_tf32(s[nt], a0, a1, a2, a3, fu(kv.x), fu(kv.y));
            }
        }

        // ---- P = ex2(S) (RNA tf32; consistent with rowsums), rowsums ----
#pragma unroll
        for (int nt = 0; nt < 8; nt++) {
#pragma unroll
            for (int e = 0; e < 4; e++)
                s[nt][e] = uf(f2tf(ex2(s[nt][e])));
            l0 += s[nt][0] + s[nt][1];
            l1 += s[nt][2] + s[nt][3];
        }

        // ---- O += P @ V : S-frag as A (k-perm); scalar V loads, stride 68 ----
#pragma unroll
        for (int kc = 0; kc < 8; kc++) {
            uint32_t a0 = fu(s[kc][0]), a1 = fu(s[kc][2]);
            uint32_t a2 = fu(s[kc][1]), a3 = fu(s[kc][3]);
            const int kb = kc * 8;
#pragma unroll
            for (int nt = 0; nt < 8; nt++) {
                uint32_t b0 = fu(Vb[(kb + 2 * t) * VSTR + nt * 8 + g]);
                uint32_t b1 = fu(Vb[(kb + 2 * t + 1) * VSTR + nt * 8 + g]);
                mma_tf32(o[nt], a0, a1, a2, a3, b0, b1);
            }
        }
        cur = (cur == 2) ? 0 : cur + 1;
    }

    // ---- rowsum reduction (within quad) and split writeout ----
    l0 += __shfl_xor_sync(0xffffffffu, l0, 1);
    l0 += __shfl_xor_sync(0xffffffffu, l0, 2);
    l1 += __shfl_xor_sync(0xffffffffu, l1, 1);
    l1 += __shfl_xor_sync(0xffffffffu, l1, 2);
    const float inv0 = 1.f / l0, inv1 = 1.f / l1;

    const size_t row = (size_t)b * NN + r0 + mb + g;
    const size_t base0 = row * INNER + h * DH;
    const size_t base1 = base0 + 8 * INNER;
#pragma unroll
    for (int nt = 0; nt < 8; nt++) {
        int c = nt * 8 + 2 * t;
        float v00 = o[nt][0] * inv0, v01 = o[nt][1] * inv0;
        float v10 = o[nt][2] * inv1, v11 = o[nt][3] * inv1;
        uint32_t h00, l00, h01, l01, h10, l10, h11, l11;
        split_tf(v00, h00, l00);
        split_tf(v01, h01, l01);
        split_tf(v10, h10, l10);
        split_tf(v11, h11, l11);
        *(float2*)&g_OH[base0 + c] = make_float2(uf(h00), uf(h01));
        *(float2*)&g_OL[base0 + c] = make_float2(uf(l00), uf(l01));
        *(float2*)&g_OH[base1 + c] = make_float2(uf(h10), uf(h11));
        *(float2*)&g_OL[base1 + c] = make_float2(uf(l10), uf(l11));
    }
}

// ---------------------------------------------------------------------------
extern "C" void kernel_launch(void* const* d_in, const int* in_sizes, int n_in,
                              void* d_out, int out_size) {
    const float* x  = (const float*)d_in[0];
    const float* Wq = (const float*)d_in[1];
    const float* Wk = (const float*)d_in[2];
    const float* Wv = (const float*)d_in[3];
    const float* Wo = (const float*)d_in[4];
    const float* bo = (const float*)d_in[5];
    float* out = (float*)d_out;

    float *Qp, *Kp, *Vp;
    cudaGetSymbolAddress((void**)&Qp, g_Q);
    cudaGetSymbolAddress((void**)&Kp, g_K);
    cudaGetSymbolAddress((void**)&Vp, g_V);

    const int smem_gemm =
        (3 * (2 * 128 * ASTR) + 3 * 32 * BSTR) * sizeof(float);      // 222720 B
    const int smem_attn = (3 * 64 * (QSTR + VSTR)) * sizeof(float);  // 107520 B

    cudaFuncSetAttribute(gemm_qkv, cudaFuncAttributeMaxDynamicSharedMemorySize,
                         smem_gemm);
    cudaFuncSetAttribute(gemm_out, cudaFuncAttributeMaxDynamicSharedMemorySize,
                         smem_gemm);
    cudaFuncSetAttribute(attn_tc6, cudaFuncAttributeMaxDynamicSharedMemorySize,
                         smem_attn);

    prep_kernel<<<(NX4 + NW4 + 255) / 256, 256>>>(x, Wq, Wk, Wv, Wo);

    gemm_qkv<<<dim3(6, ROWS / 128), 512, smem_gemm>>>(Qp, Kp, Vp);

    attn_tc6<<<dim3(NN / 128, HEADS, BB), 256, smem_attn>>>();

    gemm_out<<<dim3(2, ROWS / 128), 512, smem_gemm>>>(bo, out);
}

// round 17
// speedup vs baseline: 1.9997x; 1.3647x over previous
#include <cuda_runtime.h>
#include <cuda_fp16.h>
#include <math.h>
#include <stdint.h>

#define BB     2
#define NN     4096
#define QDIM   512
#define HEADS  8
#define DH     64
#define INNER  512
#define ROWS   (BB * NN)          // 8192
// 64^-0.5 * log2(e): S computed in log2 domain, P = ex2(S)
#define SCALE_L2E  (0.125f * 1.4426950408889634f)

#define NT     (NN / 64)
#define WN     (512 * 512)

// attn smem geometry (fp16): row = 64 halves padded to 72 (144B) -> CF loads
#define KROWB  144
#define KBUFB  (64 * KROWB)       // 9216 B per K (or V) buffer
#define VBASE  (3 * KBUFB)        // V buffers start after 3 K buffers
#define ATTN_SMEM (6 * KBUFB)     // 55296 B

// Scratch (device globals: allocation-free per harness rules)
__device__ float    g_Q[(size_t)ROWS * INNER];
__device__ float    g_K[(size_t)ROWS * INNER];
__device__ float    g_V[(size_t)ROWS * INNER];
__device__ uint16_t g_Kh[(size_t)ROWS * INNER];   // K fp16, [b,c,h*64+d]
__device__ uint16_t g_Vt[(size_t)ROWS * INNER];   // V fp16 transposed, [b,h,d,c]
__device__ float    g_OH[(size_t)ROWS * INNER];   // attention out, hi part
__device__ float    g_OL[(size_t)ROWS * INNER];   // attention out, lo part
__device__ float    g_XH[(size_t)ROWS * QDIM];    // x split hi
__device__ float    g_XL[(size_t)ROWS * QDIM];    // x split lo
__device__ float    g_WR[(size_t)4 * WN];         // Wq,Wk,Wv,Wo RNA-rounded

// ---------------------------------------------------------------------------
// helpers
// ---------------------------------------------------------------------------
__device__ __forceinline__ uint32_t f2tf(float x) {
    uint32_t u;
    asm("cvt.rna.tf32.f32 %0, %1;" : "=r"(u) : "f"(x));
    return u;
}

__device__ __forceinline__ float ex2(float x) {
    float y;
    asm("ex2.approx.ftz.f32 %0, %1;" : "=f"(y) : "f"(x));
    return y;
}

__device__ __forceinline__ uint32_t fu(float x) { return __float_as_uint(x); }
__device__ __forceinline__ float uf(uint32_t x) { return __uint_as_float(x); }

__device__ __forceinline__ uint32_t packh2(float lo, float hi) {
    __half2 h = __floats2half2_rn(lo, hi);   // .x = lo (low 16b), .y = hi
    return *(uint32_t*)&h;
}

__device__ __forceinline__ void mma_tf32(float d[4], uint32_t a0, uint32_t a1,
                                         uint32_t a2, uint32_t a3,
                                         uint32_t b0, uint32_t b1) {
    asm("mma.sync.aligned.m16n8k8.row.col.f32.tf32.tf32.f32 "
        "{%0,%1,%2,%3},{%4,%5,%6,%7},{%8,%9},{%0,%1,%2,%3};"
        : "+f"(d[0]), "+f"(d[1]), "+f"(d[2]), "+f"(d[3])
        : "r"(a0), "r"(a1), "r"(a2), "r"(a3), "r"(b0), "r"(b1));
}

__device__ __forceinline__ void mma_f16(float d[4], uint32_t a0, uint32_t a1,
                                        uint32_t a2, uint32_t a3,
                                        uint32_t b0, uint32_t b1) {
    asm("mma.sync.aligned.m16n8k16.row.col.f32.f16.f16.f32 "
        "{%0,%1,%2,%3},{%4,%5,%6,%7},{%8,%9},{%0,%1,%2,%3};"
        : "+f"(d[0]), "+f"(d[1]), "+f"(d[2]), "+f"(d[3])
        : "r"(a0), "r"(a1), "r"(a2), "r"(a3), "r"(b0), "r"(b1));
}

__device__ __forceinline__ void split_tf(float x, uint32_t& hi, uint32_t& lo) {
    hi = f2tf(x);
    lo = f2tf(x - __uint_as_float(hi));
}

__device__ __forceinline__ void split4(float4 v, float4& h, float4& l) {
    uint32_t hx, lx, hy, ly, hz, lz, hw, lw;
    split_tf(v.x, hx, lx);
    split_tf(v.y, hy, ly);
    split_tf(v.z, hz, lz);
    split_tf(v.w, hw, lw);
    h = make_float4(uf(hx), uf(hy), uf(hz), uf(hw));
    l = make_float4(uf(lx), uf(ly), uf(lz), uf(lw));
}

__device__ __forceinline__ float4 rna4(float4 v) {
    return make_float4(uf(f2tf(v.x)), uf(f2tf(v.y)), uf(f2tf(v.z)), uf(f2tf(v.w)));
}

__device__ __forceinline__ void cp16(uint32_t dst, const void* src) {
    asm volatile("cp.async.cg.shared.global [%0], [%1], 16;" :: "r"(dst), "l"(src));
}

// ---------------------------------------------------------------------------
// Prep: split x -> (XH, XL); RNA-round Wq/Wk/Wv/Wo -> g_WR. One-time.
// ---------------------------------------------------------------------------
#define NX4 (ROWS * QDIM / 4)        // 1048576 float4
#define NW4 (4 * WN / 4)             // 262144 float4

__global__ __launch_bounds__(256) void prep_kernel(const float* __restrict__ x,
                                                   const float* __restrict__ Wq,
                                                   const float* __restrict__ Wk,
                                                   const float* __restrict__ Wv,
                                                   const float* __restrict__ Wo) {
    int gid = blockIdx.x * 256 + threadIdx.x;
    if (gid < NX4) {
        float4 v = ((const float4*)x)[gid];
        float4 h, l;
        split4(v, h, l);
        ((float4*)g_XH)[gid] = h;
        ((float4*)g_XL)[gid] = l;
    } else if (gid < NX4 + NW4) {
        int g2 = gid - NX4;
        int w = g2 >> 16, off = g2 & 65535;
        const float* src = (w == 0) ? Wq : (w == 1) ? Wk : (w == 2) ? Wv : Wo;
        float4 v = ((const float4*)src)[off];
        ((float4*)(g_WR + (size_t)w * WN))[off] = rna4(v);
    }
}

// ---------------------------------------------------------------------------
// Convert: K fp32 -> fp16 (same layout); V fp32 -> fp16 TRANSPOSED per head.
// grid (NN/64, HEADS, BB), 256 threads.
// ---------------------------------------------------------------------------
__global__ __launch_bounds__(256) void convert_kernel() {
    __shared__ float ts[64][65];
    const int tid = threadIdx.x;
    const int cb = blockIdx.x * 64;
    const int h = blockIdx.y, b = blockIdx.z;

    const float* Kp = g_K + ((size_t)b * NN + cb) * INNER + h * DH;
    const float* Vp = g_V + ((size_t)b * NN + cb) * INNER + h * DH;

    // K: straight fp32 -> fp16 convert (pairwise)
#pragma unroll
    for (int i = 0; i < 8; i++) {
        int idx = tid + i * 256;       // 0..2047
        int cr = idx >> 5;             // 0..63
        int dp = (idx & 31) * 2;       // 0..62 even
        float2 v = *(const float2*)&Kp[(size_t)cr * INNER + dp];
        uint32_t hv = packh2(v.x, v.y);
        *(uint32_t*)&g_Kh[((size_t)(b * NN) + cb + cr) * INNER + h * DH + dp] = hv;
    }

    // V: stage tile, write transposed fp16
#pragma unroll
    for (int i = 0; i < 16; i++) {
        int idx = tid + i * 256;       // 0..4095
        int cr = idx >> 6, d = idx & 63;
        ts[cr][d] = Vp[(size_t)cr * INNER + d];
    }
    __syncthreads();
#pragma unroll
    for (int i = 0; i < 8; i++) {
        int idx = tid + i * 256;
        int d = idx >> 5;
        int crp = (idx & 31) * 2;
        uint32_t hv = packh2(ts[crp][d], ts[crp + 1][d]);
        *(uint32_t*)&g_Vt[((size_t)(b * HEADS + h) * DH + d) * NN + cb + crp] = hv;
    }
}

// ---------------------------------------------------------------------------
// GEMM 2xTF32, all-cp.async, triple-buffered, ONE sync per k-tile. (R14)
// ---------------------------------------------------------------------------
#define ASTR 40
#define BSTR 260
#define GN   512
#define GKT  16

struct GemmPtrs {
    const float* a0h;
    const float* a1h;
    const float* a0l;
    const float* a1l;
    const float* b0;
    const float* b1;
    const float* b2;
    const float* b3;
    uint32_t aOff0, aOff1;
    uint32_t bOff0, bOff1, bOff2, bOff3;
};

__device__ __forceinline__ void gemm_issue2(const GemmPtrs& P, int kt, int ib,
                                            uint32_t ah_u, uint32_t al_u,
                                            uint32_t bs_u) {
    const int ka = kt * 32;
    const size_t kb = (size_t)ka * GN;
    const uint32_t abuf = ah_u + (uint32_t)(ib * 128 * ASTR) * 4;
    const uint32_t lbuf = al_u + (uint32_t)(ib * 128 * ASTR) * 4;
    const uint32_t bbuf = bs_u + (uint32_t)(ib * 32 * BSTR) * 4;
    cp16(abuf + P.aOff0 * 4, P.a0h + ka);
    cp16(lbuf + P.aOff0 * 4, P.a0l + ka);
    cp16(abuf + P.aOff1 * 4, P.a1h + ka);
    cp16(lbuf + P.aOff1 * 4, P.a1l + ka);
    cp16(bbuf + P.bOff0 * 4, P.b0 + kb);
    cp16(bbuf + P.bOff1 * 4, P.b1 + kb);
    cp16(bbuf + P.bOff2 * 4, P.b2 + kb);
    cp16(bbuf + P.bOff3 * 4, P.b3 + kb);
    asm volatile("cp.async.commit_group;");
}

__device__ __forceinline__ void gemm2x_core(const float* __restrict__ Ah,
                                            const float* __restrict__ Al,
                                            const float* __restrict__ Bw,
                                            const float* __restrict__ bias,
                                            float* __restrict__ C,
                                            int m0, int n0, float* smg,
                                            bool has_bias) {
    float* Ahs = smg;
    float* Als = Ahs + 3 * 128 * ASTR;
    float* Bs  = Als + 3 * 128 * ASTR;

    const int tid = threadIdx.x;
    const int lane = tid & 31, wid = tid >> 5;
    const int t = lane & 3, g = lane >> 2;
    const int wm = wid >> 2, wn = wid & 3;

    const uint32_t ah_u = (uint32_t)__cvta_generic_to_shared(Ahs);
    const uint32_t al_u = (uint32_t)__cvta_generic_to_shared(Als);
    const uint32_t bs_u = (uint32_t)__cvta_generic_to_shared(Bs);

    GemmPtrs P;
    {
        int r0 = tid >> 3, c0 = (tid & 7) * 4;
        int r1 = (tid + 512) >> 3, c1 = ((tid + 512) & 7) * 4;
        P.a0h = Ah + (size_t)(m0 + r0) * 512 + c0;
        P.a1h = Ah + (size_t)(m0 + r1) * 512 + c1;
        P.a0l = Al + (size_t)(m0 + r0) * 512 + c0;
        P.a1l = Al + (size_t)(m0 + r1) * 512 + c1;
        P.aOff0 = (uint32_t)(r0 * ASTR + c0);
        P.aOff1 = (uint32_t)(r1 * ASTR + c1);
        int br[4], bc[4];
#pragma unroll
        for (int i = 0; i < 4; i++) {
            int idx = tid + i * 512;
            br[i] = idx >> 6;
            bc[i] = (idx & 63) * 4;
        }
        P.b0 = Bw + (size_t)br[0] * GN + n0 + bc[0];
        P.b1 = Bw + (size_t)br[1] * GN + n0 + bc[1];
        P.b2 = Bw + (size_t)br[2] * GN + n0 + bc[2];
        P.b3 = Bw + (size_t)br[3] * GN + n0 + bc[3];
        P.bOff0 = (uint32_t)(br[0] * BSTR + bc[0]);
        P.bOff1 = (uint32_t)(br[1] * BSTR + bc[1]);
        P.bOff2 = (uint32_t)(br[2] * BSTR + bc[2]);
        P.bOff3 = (uint32_t)(br[3] * BSTR + bc[3]);
    }

    gemm_issue2(P, 0, 0, ah_u, al_u, bs_u);
    gemm_issue2(P, 1, 1, ah_u, al_u, bs_u);

    float acc[2][8][4];
#pragma unroll
    for (int i = 0; i < 2; i++)
#pragma unroll
        for (int j = 0; j < 8; j++)
#pragma unroll
            for (int e = 0; e < 4; e++) acc[i][j][e] = 0.f;

    int cur = 0;
    for (int kt = 0; kt < GKT; kt++) {
        if (kt + 1 < GKT)
            asm volatile("cp.async.wait_group 1;");
        else
            asm volatile("cp.async.wait_group 0;");
        __syncthreads();

        if (kt + 2 < GKT) {
            int ib = cur + 2;
            if (ib >= 3) ib -= 3;
            gemm_issue2(P, kt + 2, ib, ah_u, al_u, bs_u);
        }

        const float* ah = Ahs + cur * 128 * ASTR;
        const float* al = Als + cur * 128 * ASTR;
        const float* bs = Bs + cur * 32 * BSTR;

#pragma unroll
        for (int kk = 0; kk < 32; kk += 8) {
            uint32_t Am[2][4], Al2[2][4];
#pragma unroll
            for (int mt = 0; mt < 2; mt++) {
                int mb = wm * 32 + mt * 16;
                float2 h0 = *(const float2*)&ah[(mb + g) * ASTR + kk + 2 * t];
                float2 h1 = *(const float2*)&ah[(mb + g + 8) * ASTR + kk + 2 * t];
                float2 l0 = *(const float2*)&al[(mb + g) * ASTR + kk + 2 * t];
                float2 l1 = *(const float2*)&al[(mb + g + 8) * ASTR + kk + 2 * t];
                Am[mt][0] = fu(h0.x); Am[mt][1] = fu(h1.x);
                Am[mt][2] = fu(h0.y); Am[mt][3] = fu(h1.y);
                Al2[mt][0] = fu(l0.x); Al2[mt][1] = fu(l1.x);
                Al2[mt][2] = fu(l0.y); Al2[mt][3] = fu(l1.y);
            }
#pragma unroll
            for (int nt = 0; nt < 8; nt++) {
                int nb = wn * 64 + nt * 8;
                uint32_t b0 = fu(bs[(kk + 2 * t) * BSTR + nb + g]);
                uint32_t b1 = fu(bs[(kk + 2 * t + 1) * BSTR + nb + g]);
#pragma unroll
                for (int mt = 0; mt < 2; mt++) {
                    mma_tf32(acc[mt][nt], Am[mt][0], Am[mt][1], Am[mt][2], Am[mt][3],
                             b0, b1);
                    mma_tf32(acc[mt][nt], Al2[mt][0], Al2[mt][1], Al2[mt][2],
                             Al2[mt][3], b0, b1);
                }
            }
        }
        cur = (cur == 2) ? 0 : cur + 1;
    }

#pragma unroll
    for (int mt = 0; mt < 2; mt++) {
#pragma unroll
        for (int nt = 0; nt < 8; nt++) {
            int r = m0 + wm * 32 + mt * 16 + g;
            int c = n0 + wn * 64 + nt * 8 + 2 * t;
            float b0 = has_bias ? bias[c] : 0.f;
            float b1 = has_bias ? bias[c + 1] : 0.f;
            float2 v0 = make_float2(acc[mt][nt][0] + b0, acc[mt][nt][1] + b1);
            float2 v1 = make_float2(acc[mt][nt][2] + b0, acc[mt][nt][3] + b1);
            *(float2*)&C[(size_t)r * GN + c] = v0;
            *(float2*)&C[(size_t)(r + 8) * GN + c] = v1;
        }
    }
}

__global__ __launch_bounds__(512, 1) void gemm_qkv(float* __restrict__ Qd,
                                                   float* __restrict__ Kd,
                                                   float* __restrict__ Vd) {
    extern __shared__ float smg[];
    const int sel = blockIdx.x >> 1;
    const float* Bw = g_WR + (size_t)sel * WN;
    float* C = (sel == 0) ? Qd : (sel == 1) ? Kd : Vd;
    gemm2x_core(g_XH, g_XL, Bw, nullptr, C, blockIdx.y * 128,
                (blockIdx.x & 1) * 256, smg, false);
}

__global__ __launch_bounds__(512, 1) void gemm_out(const float* __restrict__ bo,
                                                   float* __restrict__ out) {
    extern __shared__ float smg[];
    gemm2x_core(g_OH, g_OL, g_WR + (size_t)3 * WN, bo, out, blockIdx.y * 128,
                blockIdx.x * 256, smg, true);
}

// ---------------------------------------------------------------------------
// Flash attention v8 (fp16 m16n8k16): Q fragments fp16x2 in registers;
// K fp16 row-major + V fp16 transposed in smem (triple-buffered cp.async,
// ONE sync per tile). All B-operand loads are single 4B LDS, conflict-free
// (word offsets 4g+t at 144B row stride). P packed to fp16 in-register.
// fp16 mantissa == tf32 mantissa -> no accuracy change. 2 CTAs/SM.
// ---------------------------------------------------------------------------
__device__ __forceinline__ void attn_issue8(const uint16_t* __restrict__ Kp_h,
                                            const uint16_t* __restrict__ Vt_p,
                                            int tile, int ib, uint32_t ks_u,
                                            int tid) {
    const int cb = tile * 64;
#pragma unroll
    for (int i = 0; i < 2; i++) {
        int lin = tid + i * 256;
        int row = lin >> 3, ch = lin & 7;
        uint32_t dst = ks_u + (uint32_t)(ib * KBUFB + row * KROWB + ch * 16);
        cp16(dst, Kp_h + (size_t)(cb + row) * INNER + ch * 8);
        cp16(dst + VBASE, Vt_p + (size_t)row * NN + cb + ch * 8);
    }
    asm volatile("cp.async.commit_group;");
}

__global__ __launch_bounds__(256, 2) void attn_tc8() {
    extern __shared__ char smc[];

    const int tid = threadIdx.x;
    const int lane = tid & 31, wid = tid >> 5;
    const int t = lane & 3, g = lane >> 2;
    const int b = blockIdx.z, h = blockIdx.y;
    const int r0 = blockIdx.x * 128;
    const int mb = wid * 16;

    const uint16_t* Kp_h = g_Kh + ((size_t)b * NN) * INNER + h * DH;
    const uint16_t* Vt_p = g_Vt + (size_t)(b * HEADS + h) * DH * NN;

    const uint32_t ks_u = (uint32_t)__cvta_generic_to_shared(smc);

    // --- pre-issue KV tiles 0,1 into bufs 0,1 ---
    attn_issue8(Kp_h, Vt_p, 0, 0, ks_u, tid);
    attn_issue8(Kp_h, Vt_p, 1, 1, ks_u, tid);

    // --- Q fragments fp16x2 (fold scale*log2e): rows mb+g, mb+g+8 ---
    uint32_t qA[4][4];
    {
        const size_t row = (size_t)b * NN + r0 + mb + g;
        const float* q0 = g_Q + row * INNER + h * DH;
        const float* q1 = q0 + 8 * INNER;
#pragma unroll
        for (int kc = 0; kc < 4; kc++) {
            float2 v00 = *(const float2*)&q0[kc * 16 + 2 * t];
            float2 v01 = *(const float2*)&q0[kc * 16 + 8 + 2 * t];
            float2 v10 = *(const float2*)&q1[kc * 16 + 2 * t];
            float2 v11 = *(const float2*)&q1[kc * 16 + 8 + 2 * t];
            qA[kc][0] = packh2(v00.x * SCALE_L2E, v00.y * SCALE_L2E);  // a0
            qA[kc][1] = packh2(v10.x * SCALE_L2E, v10.y * SCALE_L2E);  // a1
            qA[kc][2] = packh2(v01.x * SCALE_L2E, v01.y * SCALE_L2E);  // a2
            qA[kc][3] = packh2(v11.x * SCALE_L2E, v11.y * SCALE_L2E);  // a3
        }
    }

    float o[8][4];
#pragma unroll
    for (int nt = 0; nt < 8; nt++)
#pragma unroll
        for (int e = 0; e < 4; e++) o[nt][e] = 0.f;
    float l0 = 0.f, l1 = 0.f;

    int cur = 0;
    for (int it = 0; it < NT; ++it) {
        if (it + 1 < NT)
            asm volatile("cp.async.wait_group 1;");
        else
            asm volatile("cp.async.wait_group 0;");
        __syncthreads();   // tile it visible; all warps done with tile it-1

        if (it + 2 < NT) {
            int ib = cur + 2;
            if (ib >= 3) ib -= 3;
            attn_issue8(Kp_h, Vt_p, it + 2, ib, ks_u, tid);
        }

        const uint32_t* KsW = (const uint32_t*)(smc + cur * KBUFB);
        const uint32_t* VtW = (const uint32_t*)(smc + VBASE + cur * KBUFB);

        // ---- S = Q @ K^T (fp16 m16n8k16): b0/b1 single 4B LDS ----
        float s[8][4];
#pragma unroll
        for (int nt = 0; nt < 8; nt++)
#pragma unroll
            for (int e = 0; e < 4; e++) s[nt][e] = 0.f;

#pragma unroll
        for (int kc = 0; kc < 4; kc++) {
#pragma unroll
            for (int nt = 0; nt < 8; nt++) {
                int base = (nt * 8 + g) * 36 + kc * 8 + t;
                uint32_t b0 = KsW[base];
                uint32_t b1 = KsW[base + 4];
                mma_f16(s[nt], qA[kc][0], qA[kc][1], qA[kc][2], qA[kc][3], b0, b1);
            }
        }

        // ---- P = ex2(S) fp32, warp-private rowsums ----
#pragma unroll
        for (int nt = 0; nt < 8; nt++) {
#pragma unroll
            for (int e = 0; e < 4; e++)
                s[nt][e] = ex2(s[nt][e]);
            l0 += s[nt][0] + s[nt][1];
            l1 += s[nt][2] + s[nt][3];
        }

        // ---- O += P @ V (fp16): A = packed P pairs, B = Vt rows ----
#pragma unroll
        for (int j = 0; j < 4; j++) {
            uint32_t a0 = packh2(s[2 * j][0], s[2 * j][1]);
            uint32_t a1 = packh2(s[2 * j][2], s[2 * j][3]);
            uint32_t a2 = packh2(s[2 * j + 1][0], s[2 * j + 1][1]);
            uint32_t a3 = packh2(s[2 * j + 1][2], s[2 * j + 1][3]);
#pragma unroll
            for (int nt = 0; nt < 8; nt++) {
                int base = (nt * 8 + g) * 36 + j * 8 + t;
                uint32_t b0 = VtW[base];
                uint32_t b1 = VtW[base + 4];
                mma_f16(o[nt], a0, a1, a2, a3, b0, b1);
            }
        }
        cur = (cur == 2) ? 0 : cur + 1;
    }

    // ---- rowsum reduction (within quad) and split writeout ----
    l0 += __shfl_xor_sync(0xffffffffu, l0, 1);
    l0 += __shfl_xor_sync(0xffffffffu, l0, 2);
    l1 += __shfl_xor_sync(0xffffffffu, l1, 1);
    l1 += __shfl_xor_sync(0xffffffffu, l1, 2);
    const float inv0 = 1.f / l0, inv1 = 1.f / l1;

    const size_t row = (size_t)b * NN + r0 + mb + g;
    const size_t base0 = row * INNER + h * DH;
    const size_t base1 = base0 + 8 * INNER;
#pragma unroll
    for (int nt = 0; nt < 8; nt++) {
        int c = nt * 8 + 2 * t;
        float v00 = o[nt][0] * inv0, v01 = o[nt][1] * inv0;
        float v10 = o[nt][2] * inv1, v11 = o[nt][3] * inv1;
        uint32_t h00, l00, h01, l01, h10, l10, h11, l11;
        split_tf(v00, h00, l00);
        split_tf(v01, h01, l01);
        split_tf(v10, h10, l10);
        split_tf(v11, h11, l11);
        *(float2*)&g_OH[base0 + c] = make_float2(uf(h00), uf(h01));
        *(float2*)&g_OL[base0 + c] = make_float2(uf(l00), uf(l01));
        *(float2*)&g_OH[base1 + c] = make_float2(uf(h10), uf(h11));
        *(float2*)&g_OL[base1 + c] = make_float2(uf(l10), uf(l11));
    }
}

// ---------------------------------------------------------------------------
extern "C" void kernel_launch(void* const* d_in, const int* in_sizes, int n_in,
                              void* d_out, int out_size) {
    const float* x  = (const float*)d_in[0];
    const float* Wq = (const float*)d_in[1];
    const float* Wk = (const float*)d_in[2];
    const float* Wv = (const float*)d_in[3];
    const float* Wo = (const float*)d_in[4];
    const float* bo = (const float*)d_in[5];
    float* out = (float*)d_out;

    float *Qp, *Kp, *Vp;
    cudaGetSymbolAddress((void**)&Qp, g_Q);
    cudaGetSymbolAddress((void**)&Kp, g_K);
    cudaGetSymbolAddress((void**)&Vp, g_V);

    const int smem_gemm =
        (3 * (2 * 128 * ASTR) + 3 * 32 * BSTR) * sizeof(float);      // 222720 B

    cudaFuncSetAttribute(gemm_qkv, cudaFuncAttributeMaxDynamicSharedMemorySize,
                         smem_gemm);
    cudaFuncSetAttribute(gemm_out, cudaFuncAttributeMaxDynamicSharedMemorySize,
                         smem_gemm);
    cudaFuncSetAttribute(attn_tc8, cudaFuncAttributeMaxDynamicSharedMemorySize,
                         ATTN_SMEM);

    prep_kernel<<<(NX4 + NW4 + 255) / 256, 256>>>(x, Wq, Wk, Wv, Wo);

    gemm_qkv<<<dim3(6, ROWS / 128), 512, smem_gemm>>>(Qp, Kp, Vp);

    convert_kernel<<<dim3(NN / 64, HEADS, BB), 256>>>();

    attn_tc8<<<dim3(NN / 128, HEADS, BB), 256, ATTN_SMEM>>>();

    gemm_out<<<dim3(2, ROWS / 128), 512, smem_gemm>>>(bo, out);
}